// round 2
// baseline (speedup 1.0000x reference)
#include <cuda_runtime.h>
#include <cuda_bf16.h>
#include <math.h>

#define EMBED   1024
#define NHEADS  16
#define HD      64
#define BATCH   4
#define SEQ     2048
#define ROWS    (BATCH * SEQ)          // 8192
#define QKVCOLS (3 * EMBED)            // 3072

// Scratch (allocation-free rule: device globals)
__device__ float g_qkv[(size_t)ROWS * QKVCOLS];   // [B*S, 3E]
__device__ float g_att[(size_t)ROWS * EMBED];     // [B*S, E] attention output (head-interleaved)

// ---------------------------------------------------------------------------
// C[M,N] = A[M,K] @ W[N,K]^T + bias[N]   (classic 128x128x16 SGEMM, 8x8/thread)
// ---------------------------------------------------------------------------
__global__ __launch_bounds__(256) void gemm_bias_kernel(
    const float* __restrict__ A, const float* __restrict__ W,
    const float* __restrict__ bias, float* __restrict__ C,
    int M, int N, int K)
{
    __shared__ float As[16][128];
    __shared__ float Ws[16][128];

    const int tid  = threadIdx.x;
    const int trow = tid >> 4;       // 0..15
    const int tcol = tid & 15;       // 0..15
    const int row0 = blockIdx.y * 128;
    const int col0 = blockIdx.x * 128;

    float acc[8][8];
#pragma unroll
    for (int i = 0; i < 8; i++)
#pragma unroll
        for (int j = 0; j < 8; j++) acc[i][j] = 0.f;

    for (int k0 = 0; k0 < K; k0 += 16) {
#pragma unroll
        for (int l = 0; l < 2; l++) {
            int f  = tid + l * 256;          // 0..511 float4 slots
            int r  = f >> 2;                 // 0..127 tile row
            int c4 = (f & 3) << 2;           // 0,4,8,12
            float4 va = *reinterpret_cast<const float4*>(A + (size_t)(row0 + r) * K + k0 + c4);
            As[c4 + 0][r] = va.x; As[c4 + 1][r] = va.y;
            As[c4 + 2][r] = va.z; As[c4 + 3][r] = va.w;
            float4 vw = *reinterpret_cast<const float4*>(W + (size_t)(col0 + r) * K + k0 + c4);
            Ws[c4 + 0][r] = vw.x; Ws[c4 + 1][r] = vw.y;
            Ws[c4 + 2][r] = vw.z; Ws[c4 + 3][r] = vw.w;
        }
        __syncthreads();

#pragma unroll
        for (int k = 0; k < 16; k++) {
            float ra[8], rb[8];
#pragma unroll
            for (int i = 0; i < 8; i++) ra[i] = As[k][trow * 8 + i];
#pragma unroll
            for (int j = 0; j < 8; j++) rb[j] = Ws[k][tcol * 8 + j];
#pragma unroll
            for (int i = 0; i < 8; i++)
#pragma unroll
                for (int j = 0; j < 8; j++) acc[i][j] += ra[i] * rb[j];
        }
        __syncthreads();
    }

#pragma unroll
    for (int i = 0; i < 8; i++) {
        int r = row0 + trow * 8 + i;
#pragma unroll
        for (int j = 0; j < 8; j += 4) {
            int c = col0 + tcol * 8 + j;
            float4 o;
            o.x = acc[i][j]     + bias[c];
            o.y = acc[i][j + 1] + bias[c + 1];
            o.z = acc[i][j + 2] + bias[c + 2];
            o.w = acc[i][j + 3] + bias[c + 3];
            *reinterpret_cast<float4*>(C + (size_t)r * N + c) = o;
        }
    }
}

// ---------------------------------------------------------------------------
// Flash attention, fp32. One CTA = 64 query rows of one (b,h).
// K/V tiles of 32 rows so total smem fits statically (<48KB, no attribute call).
// qkv layout per reference: q/k/v for head h at columns h*192 + {0,64,128}.
// smem: Qs[64][64] + Ks[32][65] + Vs[32][65] + Ps[64][32]  = 41216 B
// ---------------------------------------------------------------------------
__global__ __launch_bounds__(256) void attn_kernel(const float* __restrict__ qkv,
                                                   float* __restrict__ att)
{
    __shared__ float Qs[64 * 64];
    __shared__ float Ks[32 * 65];
    __shared__ float Vs[32 * 65];
    __shared__ float Ps[64 * 32];

    const int tid = threadIdx.x;
    const int ty  = tid >> 4;         // 0..15 -> 4 q-rows each
    const int tx  = tid & 15;         // 0..15
    const int qt  = blockIdx.x;       // q tile
    const int bh  = blockIdx.y;
    const int b   = bh >> 4;
    const int h   = bh & 15;

    const size_t rs = QKVCOLS;        // qkv row stride
    const float* base = qkv + (size_t)b * SEQ * rs + h * (3 * HD);

    // Load Q tile (pre-scaled by 1/sqrt(hd) = 0.125)
#pragma unroll
    for (int l = 0; l < 4; l++) {
        int f = l * 256 + tid;
        int r = f >> 4;
        int c = (f & 15) << 2;
        float4 v = *reinterpret_cast<const float4*>(base + (size_t)(qt * 64 + r) * rs + c);
        Qs[r * 64 + c + 0] = v.x * 0.125f;
        Qs[r * 64 + c + 1] = v.y * 0.125f;
        Qs[r * 64 + c + 2] = v.z * 0.125f;
        Qs[r * 64 + c + 3] = v.w * 0.125f;
    }

    float m_i[4], l_i[4], O[4][4];
#pragma unroll
    for (int i = 0; i < 4; i++) {
        m_i[i] = -INFINITY; l_i[i] = 0.f;
#pragma unroll
        for (int j = 0; j < 4; j++) O[i][j] = 0.f;
    }

    for (int kt = 0; kt < SEQ / 32; kt++) {
        __syncthreads();    // previous P@V reads done before K/V overwrite
        // Load K/V tile: 32 rows x 64 cols = 512 float4 slots over 256 threads
#pragma unroll
        for (int l = 0; l < 2; l++) {
            int f = l * 256 + tid;
            int r = f >> 4;                 // 0..31
            int c = (f & 15) << 2;          // 0..60
            const float* krow = base + 64 + (size_t)(kt * 32 + r) * rs + c;
            float4 kv = *reinterpret_cast<const float4*>(krow);
            Ks[r * 65 + c + 0] = kv.x; Ks[r * 65 + c + 1] = kv.y;
            Ks[r * 65 + c + 2] = kv.z; Ks[r * 65 + c + 3] = kv.w;
            float4 vv = *reinterpret_cast<const float4*>(krow + 64);
            Vs[r * 65 + c + 0] = vv.x; Vs[r * 65 + c + 1] = vv.y;
            Vs[r * 65 + c + 2] = vv.z; Vs[r * 65 + c + 3] = vv.w;
        }
        __syncthreads();

        // S tile: 64x32. s[i][j] = Q[4ty+i,:] . K[2tx+j,:]
        float s[4][2];
#pragma unroll
        for (int i = 0; i < 4; i++) { s[i][0] = 0.f; s[i][1] = 0.f; }

#pragma unroll 8
        for (int d = 0; d < 64; d++) {
            float qa[4], kb[2];
#pragma unroll
            for (int i = 0; i < 4; i++) qa[i] = Qs[(ty * 4 + i) * 64 + d];
            kb[0] = Ks[(tx * 2 + 0) * 65 + d];
            kb[1] = Ks[(tx * 2 + 1) * 65 + d];
#pragma unroll
            for (int i = 0; i < 4; i++) {
                s[i][0] += qa[i] * kb[0];
                s[i][1] += qa[i] * kb[1];
            }
        }

        // Online softmax (row reductions across the 16 lanes owning this q row)
#pragma unroll
        for (int i = 0; i < 4; i++) {
            float rm = fmaxf(s[i][0], s[i][1]);
#pragma unroll
            for (int off = 8; off >= 1; off >>= 1)
                rm = fmaxf(rm, __shfl_xor_sync(0xffffffffu, rm, off));
            float m_new = fmaxf(m_i[i], rm);
            float corr  = __expf(m_i[i] - m_new);
            float p0 = __expf(s[i][0] - m_new);
            float p1 = __expf(s[i][1] - m_new);
            Ps[(ty * 4 + i) * 32 + tx * 2 + 0] = p0;
            Ps[(ty * 4 + i) * 32 + tx * 2 + 1] = p1;
            float psum = p0 + p1;
#pragma unroll
            for (int off = 8; off >= 1; off >>= 1)
                psum += __shfl_xor_sync(0xffffffffu, psum, off);
            l_i[i] = l_i[i] * corr + psum;
            m_i[i] = m_new;
#pragma unroll
            for (int j = 0; j < 4; j++) O[i][j] *= corr;
        }
        __syncthreads();

        // O += P @ V   (P: 64x32, V: 32x64; this thread: rows 4ty.., cols 4tx..)
#pragma unroll 8
        for (int k = 0; k < 32; k++) {
            float pa[4], vb[4];
#pragma unroll
            for (int i = 0; i < 4; i++) pa[i] = Ps[(ty * 4 + i) * 32 + k];
#pragma unroll
            for (int j = 0; j < 4; j++) vb[j] = Vs[k * 65 + tx * 4 + j];
#pragma unroll
            for (int i = 0; i < 4; i++)
#pragma unroll
                for (int j = 0; j < 4; j++) O[i][j] += pa[i] * vb[j];
        }
    }

    // Final normalize + write att[b, q, h*64 + d]
#pragma unroll
    for (int i = 0; i < 4; i++) {
        int q = qt * 64 + ty * 4 + i;
        float inv = 1.f / l_i[i];
        float4 o;
        o.x = O[i][0] * inv; o.y = O[i][1] * inv;
        o.z = O[i][2] * inv; o.w = O[i][3] * inv;
        *reinterpret_cast<float4*>(att + (size_t)(b * SEQ + q) * EMBED + h * HD + tx * 4) = o;
    }
}

// ---------------------------------------------------------------------------
extern "C" void kernel_launch(void* const* d_in, const int* in_sizes, int n_in,
                              void* d_out, int out_size)
{
    (void)in_sizes; (void)n_in; (void)out_size;
    const float* x     = (const float*)d_in[0];
    const float* qkv_w = (const float*)d_in[1];
    const float* qkv_b = (const float*)d_in[2];
    const float* out_w = (const float*)d_in[3];
    const float* out_b = (const float*)d_in[4];
    float* out = (float*)d_out;

    float *qkv_buf, *att_buf;
    cudaGetSymbolAddress((void**)&qkv_buf, g_qkv);
    cudaGetSymbolAddress((void**)&att_buf, g_att);

    // 1) qkv = x @ qkv_w^T + qkv_b    [8192, 3072]
    gemm_bias_kernel<<<dim3(QKVCOLS / 128, ROWS / 128), 256>>>(
        x, qkv_w, qkv_b, qkv_buf, ROWS, QKVCOLS, EMBED);

    // 2) attention -> att [8192, 1024]
    attn_kernel<<<dim3(SEQ / 64, BATCH * NHEADS), 256>>>(qkv_buf, att_buf);

    // 3) out = att @ out_w^T + out_b  [8192, 1024]
    gemm_bias_kernel<<<dim3(EMBED / 128, ROWS / 128), 256>>>(
        att_buf, out_w, out_b, out, ROWS, EMBED, EMBED);
}

// round 4
// speedup vs baseline: 1.4407x; 1.4407x over previous
#include <cuda_runtime.h>
#include <cuda_bf16.h>
#include <math.h>
#include <stdint.h>

#define EMBED   1024
#define NHEADS  16
#define HD      64
#define BATCH   4
#define SEQ     2048
#define ROWS    (BATCH * SEQ)          // 8192
#define QKVCOLS (3 * EMBED)            // 3072

// Scratch (allocation-free rule: device globals)
__device__ float g_qkv[(size_t)ROWS * QKVCOLS];   // [B*S, 3E]
__device__ float g_att[(size_t)ROWS * EMBED];     // [B*S, E]

__device__ __forceinline__ float cvt_tf32(float x) {
    float o; asm("cvt.rna.tf32.f32 %0, %1;" : "=f"(o) : "f"(x)); return o;
}

// D += A(16x8,row) * B(8x8,col)  tf32
#define MMA_TF32(c0,c1,c2,c3,a0,a1,a2,a3,b0,b1) \
    asm volatile("mma.sync.aligned.m16n8k8.row.col.f32.tf32.tf32.f32 " \
                 "{%0,%1,%2,%3}, {%4,%5,%6,%7}, {%8,%9}, {%0,%1,%2,%3};" \
                 : "+f"(c0), "+f"(c1), "+f"(c2), "+f"(c3) \
                 : "r"(a0), "r"(a1), "r"(a2), "r"(a3), "r"(b0), "r"(b1))

// ============================================================================
// tf32 mma.sync GEMM: C[M,N] = A[M,K] @ W[N,K]^T + bias[N]
// CTA 128x128, K-tile 32. 8 warps = 4(M) x 2(N), warp tile 32x64.
// SMEM tiles padded to stride 36 floats -> conflict-free fragment loads.
// ============================================================================
#define GKT 32
#define TSTRIDE 36

__global__ __launch_bounds__(256) void gemm_mma_kernel(
    const float* __restrict__ A, const float* __restrict__ W,
    const float* __restrict__ bias, float* __restrict__ C,
    int M, int N, int K)
{
    __shared__ float As[128 * TSTRIDE];
    __shared__ float Bs[128 * TSTRIDE];

    const int tid    = threadIdx.x;
    const int lane   = tid & 31;
    const int wid    = tid >> 5;
    const int warp_m = wid & 3;        // 0..3 -> 32 rows each
    const int warp_n = wid >> 2;       // 0..1 -> 64 cols each
    const int row0   = blockIdx.y * 128;
    const int col0   = blockIdx.x * 128;

    const int lq = lane >> 2;          // 0..7
    const int lr = lane & 3;           // 0..3

    float c[2][8][4];
#pragma unroll
    for (int mi = 0; mi < 2; mi++)
#pragma unroll
        for (int ni = 0; ni < 8; ni++)
#pragma unroll
            for (int j = 0; j < 4; j++) c[mi][ni][j] = 0.f;

    const int NKT = K / GKT;
    for (int kt = 0; kt < NKT; kt++) {
        if (kt > 0) __syncthreads();
        const int k0 = kt * GKT;
        // load A,B tiles: 128 rows x 8 float4 each = 1024 slots over 256 thr
#pragma unroll
        for (int l = 0; l < 4; l++) {
            int f = tid + l * 256;
            int r = f >> 3;
            int c4 = (f & 7) << 2;
            float4 va = *reinterpret_cast<const float4*>(A + (size_t)(row0 + r) * K + k0 + c4);
            float* ap = As + r * TSTRIDE + c4;
            ap[0] = cvt_tf32(va.x); ap[1] = cvt_tf32(va.y);
            ap[2] = cvt_tf32(va.z); ap[3] = cvt_tf32(va.w);
            float4 vb = *reinterpret_cast<const float4*>(W + (size_t)(col0 + r) * K + k0 + c4);
            float* bp = Bs + r * TSTRIDE + c4;
            bp[0] = cvt_tf32(vb.x); bp[1] = cvt_tf32(vb.y);
            bp[2] = cvt_tf32(vb.z); bp[3] = cvt_tf32(vb.w);
        }
        __syncthreads();

#pragma unroll
        for (int ks = 0; ks < 4; ks++) {
            const int kk = ks * 8;
            // A fragments: 2 m-subtiles x 4 regs
            uint32_t a[2][4];
#pragma unroll
            for (int mi = 0; mi < 2; mi++) {
                const float* ab = As + (warp_m * 32 + mi * 16 + lq) * TSTRIDE + kk + lr;
                a[mi][0] = __float_as_uint(ab[0]);
                a[mi][1] = __float_as_uint(ab[8 * TSTRIDE]);
                a[mi][2] = __float_as_uint(ab[4]);
                a[mi][3] = __float_as_uint(ab[8 * TSTRIDE + 4]);
            }
            // B fragments: 8 n-subtiles x 2 regs
            uint32_t b[8][2];
#pragma unroll
            for (int ni = 0; ni < 8; ni++) {
                const float* bb = Bs + (warp_n * 64 + ni * 8 + lq) * TSTRIDE + kk + lr;
                b[ni][0] = __float_as_uint(bb[0]);
                b[ni][1] = __float_as_uint(bb[4]);
            }
#pragma unroll
            for (int mi = 0; mi < 2; mi++)
#pragma unroll
                for (int ni = 0; ni < 8; ni++)
                    MMA_TF32(c[mi][ni][0], c[mi][ni][1], c[mi][ni][2], c[mi][ni][3],
                             a[mi][0], a[mi][1], a[mi][2], a[mi][3],
                             b[ni][0], b[ni][1]);
        }
    }

    // epilogue: c0/c1 -> (row, col..col+1), c2/c3 -> (row+8, ...)
#pragma unroll
    for (int mi = 0; mi < 2; mi++) {
        int rg = row0 + warp_m * 32 + mi * 16 + lq;
#pragma unroll
        for (int ni = 0; ni < 8; ni++) {
            int cg = col0 + warp_n * 64 + ni * 8 + 2 * lr;
            float bx = bias[cg], by = bias[cg + 1];
            float2 o0 = make_float2(c[mi][ni][0] + bx, c[mi][ni][1] + by);
            float2 o1 = make_float2(c[mi][ni][2] + bx, c[mi][ni][3] + by);
            *reinterpret_cast<float2*>(C + (size_t)rg * N + cg) = o0;
            *reinterpret_cast<float2*>(C + (size_t)(rg + 8) * N + cg) = o1;
        }
    }
}

// ---------------------------------------------------------------------------
// Flash attention, fp32 (unchanged from passing R2 kernel).
// ---------------------------------------------------------------------------
__global__ __launch_bounds__(256) void attn_kernel(const float* __restrict__ qkv,
                                                   float* __restrict__ att)
{
    __shared__ float Qs[64 * 64];
    __shared__ float Ks[32 * 65];
    __shared__ float Vs[32 * 65];
    __shared__ float Ps[64 * 32];

    const int tid = threadIdx.x;
    const int ty  = tid >> 4;
    const int tx  = tid & 15;
    const int qt  = blockIdx.x;
    const int bh  = blockIdx.y;
    const int b   = bh >> 4;
    const int h   = bh & 15;

    const size_t rs = QKVCOLS;
    const float* base = qkv + (size_t)b * SEQ * rs + h * (3 * HD);

#pragma unroll
    for (int l = 0; l < 4; l++) {
        int f = l * 256 + tid;
        int r = f >> 4;
        int c = (f & 15) << 2;
        float4 v = *reinterpret_cast<const float4*>(base + (size_t)(qt * 64 + r) * rs + c);
        Qs[r * 64 + c + 0] = v.x * 0.125f;
        Qs[r * 64 + c + 1] = v.y * 0.125f;
        Qs[r * 64 + c + 2] = v.z * 0.125f;
        Qs[r * 64 + c + 3] = v.w * 0.125f;
    }

    float m_i[4], l_i[4], O[4][4];
#pragma unroll
    for (int i = 0; i < 4; i++) {
        m_i[i] = -INFINITY; l_i[i] = 0.f;
#pragma unroll
        for (int j = 0; j < 4; j++) O[i][j] = 0.f;
    }

    for (int kt = 0; kt < SEQ / 32; kt++) {
        __syncthreads();
#pragma unroll
        for (int l = 0; l < 2; l++) {
            int f = l * 256 + tid;
            int r = f >> 4;
            int c = (f & 15) << 2;
            const float* krow = base + 64 + (size_t)(kt * 32 + r) * rs + c;
            float4 kv = *reinterpret_cast<const float4*>(krow);
            Ks[r * 65 + c + 0] = kv.x; Ks[r * 65 + c + 1] = kv.y;
            Ks[r * 65 + c + 2] = kv.z; Ks[r * 65 + c + 3] = kv.w;
            float4 vv = *reinterpret_cast<const float4*>(krow + 64);
            Vs[r * 65 + c + 0] = vv.x; Vs[r * 65 + c + 1] = vv.y;
            Vs[r * 65 + c + 2] = vv.z; Vs[r * 65 + c + 3] = vv.w;
        }
        __syncthreads();

        float s[4][2];
#pragma unroll
        for (int i = 0; i < 4; i++) { s[i][0] = 0.f; s[i][1] = 0.f; }

#pragma unroll 8
        for (int d = 0; d < 64; d++) {
            float qa[4], kb[2];
#pragma unroll
            for (int i = 0; i < 4; i++) qa[i] = Qs[(ty * 4 + i) * 64 + d];
            kb[0] = Ks[(tx * 2 + 0) * 65 + d];
            kb[1] = Ks[(tx * 2 + 1) * 65 + d];
#pragma unroll
            for (int i = 0; i < 4; i++) {
                s[i][0] += qa[i] * kb[0];
                s[i][1] += qa[i] * kb[1];
            }
        }

#pragma unroll
        for (int i = 0; i < 4; i++) {
            float rm = fmaxf(s[i][0], s[i][1]);
#pragma unroll
            for (int off = 8; off >= 1; off >>= 1)
                rm = fmaxf(rm, __shfl_xor_sync(0xffffffffu, rm, off));
            float m_new = fmaxf(m_i[i], rm);
            float corr  = __expf(m_i[i] - m_new);
            float p0 = __expf(s[i][0] - m_new);
            float p1 = __expf(s[i][1] - m_new);
            Ps[(ty * 4 + i) * 32 + tx * 2 + 0] = p0;
            Ps[(ty * 4 + i) * 32 + tx * 2 + 1] = p1;
            float psum = p0 + p1;
#pragma unroll
            for (int off = 8; off >= 1; off >>= 1)
                psum += __shfl_xor_sync(0xffffffffu, psum, off);
            l_i[i] = l_i[i] * corr + psum;
            m_i[i] = m_new;
#pragma unroll
            for (int j = 0; j < 4; j++) O[i][j] *= corr;
        }
        __syncthreads();

#pragma unroll 8
        for (int k = 0; k < 32; k++) {
            float pa[4], vb[4];
#pragma unroll
            for (int i = 0; i < 4; i++) pa[i] = Ps[(ty * 4 + i) * 32 + k];
#pragma unroll
            for (int j = 0; j < 4; j++) vb[j] = Vs[k * 65 + tx * 4 + j];
#pragma unroll
            for (int i = 0; i < 4; i++)
#pragma unroll
                for (int j = 0; j < 4; j++) O[i][j] += pa[i] * vb[j];
        }
    }

#pragma unroll
    for (int i = 0; i < 4; i++) {
        int q = qt * 64 + ty * 4 + i;
        float inv = 1.f / l_i[i];
        float4 o;
        o.x = O[i][0] * inv; o.y = O[i][1] * inv;
        o.z = O[i][2] * inv; o.w = O[i][3] * inv;
        *reinterpret_cast<float4*>(att + (size_t)(b * SEQ + q) * EMBED + h * HD + tx * 4) = o;
    }
}

// ---------------------------------------------------------------------------
extern "C" void kernel_launch(void* const* d_in, const int* in_sizes, int n_in,
                              void* d_out, int out_size)
{
    (void)in_sizes; (void)n_in; (void)out_size;
    const float* x     = (const float*)d_in[0];
    const float* qkv_w = (const float*)d_in[1];
    const float* qkv_b = (const float*)d_in[2];
    const float* out_w = (const float*)d_in[3];
    const float* out_b = (const float*)d_in[4];
    float* out = (float*)d_out;

    float *qkv_buf, *att_buf;
    cudaGetSymbolAddress((void**)&qkv_buf, g_qkv);
    cudaGetSymbolAddress((void**)&att_buf, g_att);

    // 1) qkv = x @ qkv_w^T + qkv_b    [8192, 3072]
    gemm_mma_kernel<<<dim3(QKVCOLS / 128, ROWS / 128), 256>>>(
        x, qkv_w, qkv_b, qkv_buf, ROWS, QKVCOLS, EMBED);

    // 2) attention -> att [8192, 1024]
    attn_kernel<<<dim3(SEQ / 64, BATCH * NHEADS), 256>>>(qkv_buf, att_buf);

    // 3) out = att @ out_w^T + out_b  [8192, 1024]
    gemm_mma_kernel<<<dim3(EMBED / 128, ROWS / 128), 256>>>(
        att_buf, out_w, out_b, out, ROWS, EMBED, EMBED);
}

// round 5
// speedup vs baseline: 3.2979x; 2.2890x over previous
#include <cuda_runtime.h>
#include <cuda_bf16.h>
#include <math.h>
#include <stdint.h>

#define EMBED   1024
#define NHEADS  16
#define HD      64
#define BATCH   4
#define SEQ     2048
#define ROWS    (BATCH * SEQ)          // 8192
#define QKVCOLS (3 * EMBED)            // 3072

// Scratch (allocation-free rule: device globals)
__device__ float g_qkv[(size_t)ROWS * QKVCOLS];   // [B*S, 3E]
__device__ float g_att[(size_t)ROWS * EMBED];     // [B*S, E]

__device__ __forceinline__ float cvt_tf32(float x) {
    float o; asm("cvt.rna.tf32.f32 %0, %1;" : "=f"(o) : "f"(x)); return o;
}

// D += A(16x8,row) * B(8x8,col)  tf32
#define MMA_TF32(c0,c1,c2,c3,a0,a1,a2,a3,b0,b1) \
    asm volatile("mma.sync.aligned.m16n8k8.row.col.f32.tf32.tf32.f32 " \
                 "{%0,%1,%2,%3}, {%4,%5,%6,%7}, {%8,%9}, {%0,%1,%2,%3};" \
                 : "+f"(c0), "+f"(c1), "+f"(c2), "+f"(c3) \
                 : "r"(a0), "r"(a1), "r"(a2), "r"(a3), "r"(b0), "r"(b1))

// ============================================================================
// tf32 mma.sync GEMM: C[M,N] = A[M,K] @ W[N,K]^T + bias[N]   (unchanged, R4)
// ============================================================================
#define GKT 32
#define TSTRIDE 36

__global__ __launch_bounds__(256) void gemm_mma_kernel(
    const float* __restrict__ A, const float* __restrict__ W,
    const float* __restrict__ bias, float* __restrict__ C,
    int M, int N, int K)
{
    __shared__ float As[128 * TSTRIDE];
    __shared__ float Bs[128 * TSTRIDE];

    const int tid    = threadIdx.x;
    const int lane   = tid & 31;
    const int wid    = tid >> 5;
    const int warp_m = wid & 3;
    const int warp_n = wid >> 2;
    const int row0   = blockIdx.y * 128;
    const int col0   = blockIdx.x * 128;

    const int lq = lane >> 2;
    const int lr = lane & 3;

    float c[2][8][4];
#pragma unroll
    for (int mi = 0; mi < 2; mi++)
#pragma unroll
        for (int ni = 0; ni < 8; ni++)
#pragma unroll
            for (int j = 0; j < 4; j++) c[mi][ni][j] = 0.f;

    const int NKT = K / GKT;
    for (int kt = 0; kt < NKT; kt++) {
        if (kt > 0) __syncthreads();
        const int k0 = kt * GKT;
#pragma unroll
        for (int l = 0; l < 4; l++) {
            int f = tid + l * 256;
            int r = f >> 3;
            int c4 = (f & 7) << 2;
            float4 va = *reinterpret_cast<const float4*>(A + (size_t)(row0 + r) * K + k0 + c4);
            float* ap = As + r * TSTRIDE + c4;
            ap[0] = cvt_tf32(va.x); ap[1] = cvt_tf32(va.y);
            ap[2] = cvt_tf32(va.z); ap[3] = cvt_tf32(va.w);
            float4 vb = *reinterpret_cast<const float4*>(W + (size_t)(col0 + r) * K + k0 + c4);
            float* bp = Bs + r * TSTRIDE + c4;
            bp[0] = cvt_tf32(vb.x); bp[1] = cvt_tf32(vb.y);
            bp[2] = cvt_tf32(vb.z); bp[3] = cvt_tf32(vb.w);
        }
        __syncthreads();

#pragma unroll
        for (int ks = 0; ks < 4; ks++) {
            const int kk = ks * 8;
            uint32_t a[2][4];
#pragma unroll
            for (int mi = 0; mi < 2; mi++) {
                const float* ab = As + (warp_m * 32 + mi * 16 + lq) * TSTRIDE + kk + lr;
                a[mi][0] = __float_as_uint(ab[0]);
                a[mi][1] = __float_as_uint(ab[8 * TSTRIDE]);
                a[mi][2] = __float_as_uint(ab[4]);
                a[mi][3] = __float_as_uint(ab[8 * TSTRIDE + 4]);
            }
            uint32_t b[8][2];
#pragma unroll
            for (int ni = 0; ni < 8; ni++) {
                const float* bb = Bs + (warp_n * 64 + ni * 8 + lq) * TSTRIDE + kk + lr;
                b[ni][0] = __float_as_uint(bb[0]);
                b[ni][1] = __float_as_uint(bb[4]);
            }
#pragma unroll
            for (int mi = 0; mi < 2; mi++)
#pragma unroll
                for (int ni = 0; ni < 8; ni++)
                    MMA_TF32(c[mi][ni][0], c[mi][ni][1], c[mi][ni][2], c[mi][ni][3],
                             a[mi][0], a[mi][1], a[mi][2], a[mi][3],
                             b[ni][0], b[ni][1]);
        }
    }

#pragma unroll
    for (int mi = 0; mi < 2; mi++) {
        int rg = row0 + warp_m * 32 + mi * 16 + lq;
#pragma unroll
        for (int ni = 0; ni < 8; ni++) {
            int cg = col0 + warp_n * 64 + ni * 8 + 2 * lr;
            float bx = bias[cg], by = bias[cg + 1];
            float2 o0 = make_float2(c[mi][ni][0] + bx, c[mi][ni][1] + by);
            float2 o1 = make_float2(c[mi][ni][2] + bx, c[mi][ni][3] + by);
            *reinterpret_cast<float2*>(C + (size_t)rg * N + cg) = o0;
            *reinterpret_cast<float2*>(C + (size_t)(rg + 8) * N + cg) = o1;
        }
    }
}

// ============================================================================
// Tensor-core flash attention (tf32 mma.sync).
// CTA: 256 thr = 8 warps, 128 q-rows of one (b,h); warp w owns rows 16w..16w+15.
// kv-tiles of 32. K,V staged natural [kv][hd] stride 68; P per-warp [16][36].
// smem buffer 8960 floats (35840 B), aliased for Q staging (128x68 <= 8704fl).
// ============================================================================
#define KSTR 68
#define PSTR 36

__global__ __launch_bounds__(256) void attn_mma_kernel(const float* __restrict__ qkv,
                                                       float* __restrict__ att)
{
    __shared__ float sm[8960];

    const int tid  = threadIdx.x;
    const int lane = tid & 31;
    const int w    = tid >> 5;        // 0..7
    const int lq   = lane >> 2;       // 0..7
    const int lr   = lane & 3;        // 0..3

    const int qt = blockIdx.x;        // 0..15
    const int bh = blockIdx.y;
    const int b  = bh >> 4;
    const int h  = bh & 15;

    const size_t rs = QKVCOLS;
    const float* base = qkv + (size_t)b * SEQ * rs + h * (3 * HD);

    // ---- stage Q tile [128][64] -> sm (stride 68), scaled + tf32 ----
#pragma unroll
    for (int l = 0; l < 8; l++) {
        int f = tid + l * 256;
        int r = f >> 4;
        int c = (f & 15) << 2;
        float4 v = *reinterpret_cast<const float4*>(base + (size_t)(qt * 128 + r) * rs + c);
        float* qp = sm + r * KSTR + c;
        qp[0] = cvt_tf32(v.x * 0.125f); qp[1] = cvt_tf32(v.y * 0.125f);
        qp[2] = cvt_tf32(v.z * 0.125f); qp[3] = cvt_tf32(v.w * 0.125f);
    }
    __syncthreads();

    // ---- persistent Q fragments: 8 k-steps x 4 regs ----
    uint32_t aq[8][4];
    {
        const float* qb = sm + (w * 16 + lq) * KSTR;
#pragma unroll
        for (int kk = 0; kk < 8; kk++) {
            aq[kk][0] = __float_as_uint(qb[kk * 8 + lr]);
            aq[kk][1] = __float_as_uint(qb[8 * KSTR + kk * 8 + lr]);
            aq[kk][2] = __float_as_uint(qb[kk * 8 + lr + 4]);
            aq[kk][3] = __float_as_uint(qb[8 * KSTR + kk * 8 + lr + 4]);
        }
    }
    __syncthreads();

    float* Ks  = sm;                       // [32][68]
    float* Vs  = sm + 32 * KSTR;           // [32][68]
    float* Psw = sm + 64 * KSTR + w * 16 * PSTR;   // per-warp [16][36]

    float o[8][4];
#pragma unroll
    for (int ni = 0; ni < 8; ni++)
#pragma unroll
        for (int j = 0; j < 4; j++) o[ni][j] = 0.f;
    float m0 = -INFINITY, m1 = -INFINITY, l0 = 0.f, l1 = 0.f;

    for (int kt = 0; kt < SEQ / 32; kt++) {
        // load K,V tile (32 rows x 64 cols each; 512 float4 slots over 256 thr)
#pragma unroll
        for (int l = 0; l < 2; l++) {
            int f = tid + l * 256;
            int r = f >> 4;
            int c = (f & 15) << 2;
            const float* kr = base + 64 + (size_t)(kt * 32 + r) * rs + c;
            float4 kv4 = *reinterpret_cast<const float4*>(kr);
            float* kp = Ks + r * KSTR + c;
            kp[0] = cvt_tf32(kv4.x); kp[1] = cvt_tf32(kv4.y);
            kp[2] = cvt_tf32(kv4.z); kp[3] = cvt_tf32(kv4.w);
            float4 vv4 = *reinterpret_cast<const float4*>(kr + 64);
            float* vp = Vs + r * KSTR + c;
            vp[0] = cvt_tf32(vv4.x); vp[1] = cvt_tf32(vv4.y);
            vp[2] = cvt_tf32(vv4.z); vp[3] = cvt_tf32(vv4.w);
        }
        __syncthreads();

        // ---- S = Q K^T : 4 n-subtiles (kv) x 8 k-steps (hd) ----
        float s[4][4];
#pragma unroll
        for (int ni = 0; ni < 4; ni++)
#pragma unroll
            for (int j = 0; j < 4; j++) s[ni][j] = 0.f;

#pragma unroll
        for (int kk = 0; kk < 8; kk++) {
            uint32_t bk[4][2];
#pragma unroll
            for (int ni = 0; ni < 4; ni++) {
                const float* kb = Ks + (ni * 8 + lq) * KSTR + kk * 8 + lr;
                bk[ni][0] = __float_as_uint(kb[0]);
                bk[ni][1] = __float_as_uint(kb[4]);
            }
#pragma unroll
            for (int ni = 0; ni < 4; ni++)
                MMA_TF32(s[ni][0], s[ni][1], s[ni][2], s[ni][3],
                         aq[kk][0], aq[kk][1], aq[kk][2], aq[kk][3],
                         bk[ni][0], bk[ni][1]);
        }

        // ---- online softmax on fragments (rows lq, lq+8) ----
        float mx0 = -INFINITY, mx1 = -INFINITY;
#pragma unroll
        for (int ni = 0; ni < 4; ni++) {
            mx0 = fmaxf(mx0, fmaxf(s[ni][0], s[ni][1]));
            mx1 = fmaxf(mx1, fmaxf(s[ni][2], s[ni][3]));
        }
        mx0 = fmaxf(mx0, __shfl_xor_sync(0xffffffffu, mx0, 1));
        mx0 = fmaxf(mx0, __shfl_xor_sync(0xffffffffu, mx0, 2));
        mx1 = fmaxf(mx1, __shfl_xor_sync(0xffffffffu, mx1, 1));
        mx1 = fmaxf(mx1, __shfl_xor_sync(0xffffffffu, mx1, 2));

        float mn0 = fmaxf(m0, mx0);
        float mn1 = fmaxf(m1, mx1);
        float corr0 = __expf(m0 - mn0);
        float corr1 = __expf(m1 - mn1);
        m0 = mn0; m1 = mn1;

        float sum0 = 0.f, sum1 = 0.f;
#pragma unroll
        for (int ni = 0; ni < 4; ni++) {
            float p0 = __expf(s[ni][0] - m0);
            float p1 = __expf(s[ni][1] - m0);
            float p2 = __expf(s[ni][2] - m1);
            float p3 = __expf(s[ni][3] - m1);
            sum0 += p0 + p1;
            sum1 += p2 + p3;
            float2 w0 = make_float2(cvt_tf32(p0), cvt_tf32(p1));
            float2 w1 = make_float2(cvt_tf32(p2), cvt_tf32(p3));
            *reinterpret_cast<float2*>(Psw + lq * PSTR + ni * 8 + 2 * lr) = w0;
            *reinterpret_cast<float2*>(Psw + (lq + 8) * PSTR + ni * 8 + 2 * lr) = w1;
        }
        sum0 += __shfl_xor_sync(0xffffffffu, sum0, 1);
        sum0 += __shfl_xor_sync(0xffffffffu, sum0, 2);
        sum1 += __shfl_xor_sync(0xffffffffu, sum1, 1);
        sum1 += __shfl_xor_sync(0xffffffffu, sum1, 2);
        l0 = l0 * corr0 + sum0;
        l1 = l1 * corr1 + sum1;

#pragma unroll
        for (int ni = 0; ni < 8; ni++) {
            o[ni][0] *= corr0; o[ni][1] *= corr0;
            o[ni][2] *= corr1; o[ni][3] *= corr1;
        }
        __syncwarp();

        // ---- O += P V : 8 n-subtiles (hd) x 4 k-steps (kv) ----
#pragma unroll
        for (int kk = 0; kk < 4; kk++) {
            uint32_t pa[4];
            const float* pb = Psw + lq * PSTR + kk * 8 + lr;
            pa[0] = __float_as_uint(pb[0]);
            pa[1] = __float_as_uint(pb[8 * PSTR]);
            pa[2] = __float_as_uint(pb[4]);
            pa[3] = __float_as_uint(pb[8 * PSTR + 4]);
#pragma unroll
            for (int ni = 0; ni < 8; ni++) {
                uint32_t vb0 = __float_as_uint(Vs[(kk * 8 + lr) * KSTR + ni * 8 + lq]);
                uint32_t vb1 = __float_as_uint(Vs[(kk * 8 + lr + 4) * KSTR + ni * 8 + lq]);
                MMA_TF32(o[ni][0], o[ni][1], o[ni][2], o[ni][3],
                         pa[0], pa[1], pa[2], pa[3], vb0, vb1);
            }
        }
        __syncthreads();
    }

    // ---- finalize + write att[b, q, h*64 + col] ----
    float inv0 = 1.f / l0;
    float inv1 = 1.f / l1;
    int gq = qt * 128 + w * 16 + lq;
    float* orow0 = att + (size_t)(b * SEQ + gq) * EMBED + h * HD;
    float* orow1 = orow0 + (size_t)8 * EMBED;
#pragma unroll
    for (int ni = 0; ni < 8; ni++) {
        int col = ni * 8 + 2 * lr;
        *reinterpret_cast<float2*>(orow0 + col) =
            make_float2(o[ni][0] * inv0, o[ni][1] * inv0);
        *reinterpret_cast<float2*>(orow1 + col) =
            make_float2(o[ni][2] * inv1, o[ni][3] * inv1);
    }
}

// ---------------------------------------------------------------------------
extern "C" void kernel_launch(void* const* d_in, const int* in_sizes, int n_in,
                              void* d_out, int out_size)
{
    (void)in_sizes; (void)n_in; (void)out_size;
    const float* x     = (const float*)d_in[0];
    const float* qkv_w = (const float*)d_in[1];
    const float* qkv_b = (const float*)d_in[2];
    const float* out_w = (const float*)d_in[3];
    const float* out_b = (const float*)d_in[4];
    float* out = (float*)d_out;

    float *qkv_buf, *att_buf;
    cudaGetSymbolAddress((void**)&qkv_buf, g_qkv);
    cudaGetSymbolAddress((void**)&att_buf, g_att);

    // 1) qkv = x @ qkv_w^T + qkv_b    [8192, 3072]
    gemm_mma_kernel<<<dim3(QKVCOLS / 128, ROWS / 128), 256>>>(
        x, qkv_w, qkv_b, qkv_buf, ROWS, QKVCOLS, EMBED);

    // 2) attention -> att [8192, 1024]
    attn_mma_kernel<<<dim3(SEQ / 128, BATCH * NHEADS), 256>>>(qkv_buf, att_buf);

    // 3) out = att @ out_w^T + out_b  [8192, 1024]
    gemm_mma_kernel<<<dim3(EMBED / 128, ROWS / 128), 256>>>(
        att_buf, out_w, out_b, out, ROWS, EMBED, EMBED);
}